// round 2
// baseline (speedup 1.0000x reference)
#include <cuda_runtime.h>

// CompositeValueNoise with in-launch spatial counting sort.
// out[i] = sum over res in {16,32,64,128} of (16/res) * smoothstep-trilerp(V_res, x[i]*res)

#define MAX_POINTS 2000000
#define NB 32768            // 32^3 buckets (V32 cells)
#define SCAN_THREADS 1024
#define PER_THREAD (NB / SCAN_THREADS)

__device__ int    g_hist[NB];
__device__ int    g_off[NB];
__device__ float4 g_xs[MAX_POINTS];   // sorted points; .w carries original index bits

// ---------------------------------------------------------------------------
// noise math
// ---------------------------------------------------------------------------
__device__ __forceinline__ float4 lerp4(const float4 a, const float4 b, const float t) {
    return make_float4(fmaf(t, b.x - a.x, a.x),
                       fmaf(t, b.y - a.y, a.y),
                       fmaf(t, b.z - a.z, a.z),
                       fmaf(t, b.w - a.w, a.w));
}

template <int RES>
__device__ __forceinline__ float4 noise_level(const float4* __restrict__ V,
                                              float px, float py, float pz) {
    const float r = (float)RES;
    float sx = px * r, sy = py * r, sz = pz * r;
    float fx = floorf(sx), fy = floorf(sy), fz = floorf(sz);
    float tx = sx - fx, ty = sy - fy, tz = sz - fz;
    int ix = min((int)fx, RES - 1);
    int iy = min((int)fy, RES - 1);
    int iz = min((int)fz, RES - 1);

    float wx = (3.0f - 2.0f * tx) * tx * tx;
    float wy = (3.0f - 2.0f * ty) * ty * ty;
    float wz = (3.0f - 2.0f * tz) * tz * tz;

    const int S  = RES + 1;
    const int SY = S;
    const int SX = S * S;
    int base = (ix * S + iy) * S + iz;

    float4 c000 = __ldg(V + base);
    float4 c001 = __ldg(V + base + 1);
    float4 c010 = __ldg(V + base + SY);
    float4 c011 = __ldg(V + base + SY + 1);
    float4 c100 = __ldg(V + base + SX);
    float4 c101 = __ldg(V + base + SX + 1);
    float4 c110 = __ldg(V + base + SX + SY);
    float4 c111 = __ldg(V + base + SX + SY + 1);

    float4 az = lerp4(c000, c001, wz);
    float4 bz = lerp4(c010, c011, wz);
    float4 cz = lerp4(c100, c101, wz);
    float4 dz = lerp4(c110, c111, wz);
    float4 ay = lerp4(az, bz, wy);
    float4 by = lerp4(cz, dz, wy);
    return lerp4(ay, by, wx);
}

__device__ __forceinline__ int bucket_key(float px, float py, float pz) {
    int kx = min((int)(px * 32.0f), 31);
    int ky = min((int)(py * 32.0f), 31);
    int kz = min((int)(pz * 32.0f), 31);
    return (kx << 10) | (ky << 5) | kz;
}

// ---------------------------------------------------------------------------
// sort pipeline
// ---------------------------------------------------------------------------
__global__ void zero_hist_kernel() {
    int i = blockIdx.x * blockDim.x + threadIdx.x;
    if (i < NB) g_hist[i] = 0;
}

__global__ void histo_kernel(const float* __restrict__ x, int n) {
    int i = blockIdx.x * blockDim.x + threadIdx.x;
    if (i >= n) return;
    float px = __ldg(x + 3 * i);
    float py = __ldg(x + 3 * i + 1);
    float pz = __ldg(x + 3 * i + 2);
    atomicAdd(&g_hist[bucket_key(px, py, pz)], 1);
}

__global__ void __launch_bounds__(SCAN_THREADS)
scan_kernel() {
    __shared__ int sm[SCAN_THREADS];
    int tid = threadIdx.x;
    int base = tid * PER_THREAD;
    int s = 0;
    #pragma unroll
    for (int j = 0; j < PER_THREAD; j++) s += g_hist[base + j];
    sm[tid] = s;
    __syncthreads();
    // Hillis-Steele inclusive scan over 1024 partials
    for (int off = 1; off < SCAN_THREADS; off <<= 1) {
        int v = (tid >= off) ? sm[tid - off] : 0;
        __syncthreads();
        sm[tid] += v;
        __syncthreads();
    }
    int run = sm[tid] - s;   // exclusive prefix of this thread's chunk
    #pragma unroll
    for (int j = 0; j < PER_THREAD; j++) {
        int h = g_hist[base + j];
        g_off[base + j] = run;
        run += h;
    }
}

__global__ void scatter_kernel(const float* __restrict__ x, int n) {
    int i = blockIdx.x * blockDim.x + threadIdx.x;
    if (i >= n) return;
    float px = __ldg(x + 3 * i);
    float py = __ldg(x + 3 * i + 1);
    float pz = __ldg(x + 3 * i + 2);
    int pos = atomicAdd(&g_off[bucket_key(px, py, pz)], 1);
    g_xs[pos] = make_float4(px, py, pz, __int_as_float(i));
}

// ---------------------------------------------------------------------------
// main kernel: coalesced read of sorted points, divergent scatter of result
// ---------------------------------------------------------------------------
__global__ void __launch_bounds__(256)
noise_sorted_kernel(const float4* __restrict__ V16,
                    const float4* __restrict__ V32,
                    const float4* __restrict__ V64,
                    const float4* __restrict__ V128,
                    float4* __restrict__ out,
                    int n) {
    int i = blockIdx.x * blockDim.x + threadIdx.x;
    if (i >= n) return;

    float4 p = g_xs[i];
    float px = p.x, py = p.y, pz = p.z;
    int orig = __float_as_int(p.w);

    float4 acc = noise_level<16>(V16, px, py, pz);
    float4 t;

    t = noise_level<32>(V32, px, py, pz);
    acc.x = fmaf(0.5f, t.x, acc.x);
    acc.y = fmaf(0.5f, t.y, acc.y);
    acc.z = fmaf(0.5f, t.z, acc.z);
    acc.w = fmaf(0.5f, t.w, acc.w);

    t = noise_level<64>(V64, px, py, pz);
    acc.x = fmaf(0.25f, t.x, acc.x);
    acc.y = fmaf(0.25f, t.y, acc.y);
    acc.z = fmaf(0.25f, t.z, acc.z);
    acc.w = fmaf(0.25f, t.w, acc.w);

    t = noise_level<128>(V128, px, py, pz);
    acc.x = fmaf(0.125f, t.x, acc.x);
    acc.y = fmaf(0.125f, t.y, acc.y);
    acc.z = fmaf(0.125f, t.z, acc.z);
    acc.w = fmaf(0.125f, t.w, acc.w);

    out[orig] = acc;
}

// ---------------------------------------------------------------------------
// fallback (unsorted) for safety if n exceeds static scratch
// ---------------------------------------------------------------------------
__global__ void __launch_bounds__(256)
noise_direct_kernel(const float* __restrict__ x,
                    const float4* __restrict__ V16,
                    const float4* __restrict__ V32,
                    const float4* __restrict__ V64,
                    const float4* __restrict__ V128,
                    float4* __restrict__ out,
                    int n) {
    int i = blockIdx.x * blockDim.x + threadIdx.x;
    if (i >= n) return;
    float px = x[3 * i], py = x[3 * i + 1], pz = x[3 * i + 2];
    float4 acc = noise_level<16>(V16, px, py, pz);
    float4 t;
    t = noise_level<32>(V32, px, py, pz);
    acc.x = fmaf(0.5f, t.x, acc.x); acc.y = fmaf(0.5f, t.y, acc.y);
    acc.z = fmaf(0.5f, t.z, acc.z); acc.w = fmaf(0.5f, t.w, acc.w);
    t = noise_level<64>(V64, px, py, pz);
    acc.x = fmaf(0.25f, t.x, acc.x); acc.y = fmaf(0.25f, t.y, acc.y);
    acc.z = fmaf(0.25f, t.z, acc.z); acc.w = fmaf(0.25f, t.w, acc.w);
    t = noise_level<128>(V128, px, py, pz);
    acc.x = fmaf(0.125f, t.x, acc.x); acc.y = fmaf(0.125f, t.y, acc.y);
    acc.z = fmaf(0.125f, t.z, acc.z); acc.w = fmaf(0.125f, t.w, acc.w);
    out[i] = acc;
}

extern "C" void kernel_launch(void* const* d_in, const int* in_sizes, int n_in,
                              void* d_out, int out_size) {
    const float*  x    = (const float*)d_in[0];
    const float4* V16  = (const float4*)d_in[1];
    const float4* V32  = (const float4*)d_in[2];
    const float4* V64  = (const float4*)d_in[3];
    const float4* V128 = (const float4*)d_in[4];
    float4* out = (float4*)d_out;

    int n = in_sizes[0] / 3;
    int threads = 256;
    int blocks = (n + threads - 1) / threads;

    if (n > MAX_POINTS) {
        noise_direct_kernel<<<blocks, threads>>>(x, V16, V32, V64, V128, out, n);
        return;
    }

    zero_hist_kernel<<<(NB + 255) / 256, 256>>>();
    histo_kernel<<<blocks, threads>>>(x, n);
    scan_kernel<<<1, SCAN_THREADS>>>();
    scatter_kernel<<<blocks, threads>>>(x, n);
    noise_sorted_kernel<<<blocks, threads>>>(V16, V32, V64, V128, out, n);
}

// round 4
// speedup vs baseline: 1.0874x; 1.0874x over previous
#include <cuda_runtime.h>

// CompositeValueNoise, bucket-tiled:
//   1) counting-sort points by V32 cell (32^3 buckets)
//   2) one CTA per bucket stages the bucket's V-tile footprint (all 4 levels,
//      ~2.7 KB) into shared memory, then evaluates its points from smem.

#define MAX_POINTS 2000000
#define NB 32768            // 32^3 buckets
#define SCAN_THREADS 1024
#define PER_THREAD (NB / SCAN_THREADS)
#define BUCKET_THREADS 64

__device__ int    g_hist[NB];
__device__ int    g_off[NB];
__device__ float4 g_xs[MAX_POINTS];   // sorted points; .w carries original index

// ---------------------------------------------------------------------------
// math helpers
// ---------------------------------------------------------------------------
__device__ __forceinline__ float4 lerp4(const float4 a, const float4 b, const float t) {
    return make_float4(fmaf(t, b.x - a.x, a.x),
                       fmaf(t, b.y - a.y, a.y),
                       fmaf(t, b.z - a.z, a.z),
                       fmaf(t, b.w - a.w, a.w));
}

// Trilerp one level out of a smem tile of dim T^3 whose (0,0,0) point is grid
// point (bx,by,bz) of the RES-level grid.
template <int RES, int T>
__device__ __forceinline__ float4 noise_smem(const float4* __restrict__ sm,
                                             int bx, int by, int bz,
                                             float px, float py, float pz) {
    const float r = (float)RES;
    float sx = px * r, sy = py * r, sz = pz * r;
    float fx = floorf(sx), fy = floorf(sy), fz = floorf(sz);
    float tx = sx - fx, ty = sy - fy, tz = sz - fz;
    int lx = (int)fx - bx;
    int ly = (int)fy - by;
    int lz = (int)fz - bz;

    float wx = (3.0f - 2.0f * tx) * tx * tx;
    float wy = (3.0f - 2.0f * ty) * ty * ty;
    float wz = (3.0f - 2.0f * tz) * tz * tz;

    int idx = (lx * T + ly) * T + lz;
    float4 c000 = sm[idx];
    float4 c001 = sm[idx + 1];
    float4 c010 = sm[idx + T];
    float4 c011 = sm[idx + T + 1];
    float4 c100 = sm[idx + T * T];
    float4 c101 = sm[idx + T * T + 1];
    float4 c110 = sm[idx + T * T + T];
    float4 c111 = sm[idx + T * T + T + 1];

    float4 az = lerp4(c000, c001, wz);
    float4 bz4 = lerp4(c010, c011, wz);
    float4 cz = lerp4(c100, c101, wz);
    float4 dz = lerp4(c110, c111, wz);
    float4 ay = lerp4(az, bz4, wy);
    float4 by4 = lerp4(cz, dz, wy);
    return lerp4(ay, by4, wx);
}

// global-gather version (fallback path)
template <int RES>
__device__ __forceinline__ float4 noise_level(const float4* __restrict__ V,
                                              float px, float py, float pz) {
    const float r = (float)RES;
    float sx = px * r, sy = py * r, sz = pz * r;
    float fx = floorf(sx), fy = floorf(sy), fz = floorf(sz);
    float tx = sx - fx, ty = sy - fy, tz = sz - fz;
    int ix = min((int)fx, RES - 1);
    int iy = min((int)fy, RES - 1);
    int iz = min((int)fz, RES - 1);
    float wx = (3.0f - 2.0f * tx) * tx * tx;
    float wy = (3.0f - 2.0f * ty) * ty * ty;
    float wz = (3.0f - 2.0f * tz) * tz * tz;
    const int S = RES + 1, SY = S, SX = S * S;
    int base = (ix * S + iy) * S + iz;
    float4 c000 = __ldg(V + base);
    float4 c001 = __ldg(V + base + 1);
    float4 c010 = __ldg(V + base + SY);
    float4 c011 = __ldg(V + base + SY + 1);
    float4 c100 = __ldg(V + base + SX);
    float4 c101 = __ldg(V + base + SX + 1);
    float4 c110 = __ldg(V + base + SX + SY);
    float4 c111 = __ldg(V + base + SX + SY + 1);
    float4 az = lerp4(c000, c001, wz);
    float4 bz = lerp4(c010, c011, wz);
    float4 cz = lerp4(c100, c101, wz);
    float4 dz = lerp4(c110, c111, wz);
    float4 ay = lerp4(az, bz, wy);
    float4 by = lerp4(cz, dz, wy);
    return lerp4(ay, by, wx);
}

__device__ __forceinline__ int bucket_key(float px, float py, float pz) {
    int kx = min((int)(px * 32.0f), 31);
    int ky = min((int)(py * 32.0f), 31);
    int kz = min((int)(pz * 32.0f), 31);
    return (kx << 10) | (ky << 5) | kz;
}

// ---------------------------------------------------------------------------
// sort pipeline
// ---------------------------------------------------------------------------
__global__ void zero_hist_kernel() {
    int i = blockIdx.x * blockDim.x + threadIdx.x;
    if (i < NB) g_hist[i] = 0;
}

__global__ void histo_kernel(const float* __restrict__ x, int n) {
    int i = blockIdx.x * blockDim.x + threadIdx.x;
    if (i >= n) return;
    float px = __ldg(x + 3 * i);
    float py = __ldg(x + 3 * i + 1);
    float pz = __ldg(x + 3 * i + 2);
    atomicAdd(&g_hist[bucket_key(px, py, pz)], 1);
}

__global__ void __launch_bounds__(SCAN_THREADS)
scan_kernel() {
    __shared__ int sm[SCAN_THREADS];
    int tid = threadIdx.x;
    int base = tid * PER_THREAD;
    int s = 0;
    #pragma unroll
    for (int j = 0; j < PER_THREAD; j++) s += g_hist[base + j];
    sm[tid] = s;
    __syncthreads();
    for (int off = 1; off < SCAN_THREADS; off <<= 1) {
        int v = (tid >= off) ? sm[tid - off] : 0;
        __syncthreads();
        sm[tid] += v;
        __syncthreads();
    }
    int run = sm[tid] - s;
    #pragma unroll
    for (int j = 0; j < PER_THREAD; j++) {
        int h = g_hist[base + j];
        g_off[base + j] = run;
        run += h;
    }
}

__global__ void scatter_kernel(const float* __restrict__ x, int n) {
    int i = blockIdx.x * blockDim.x + threadIdx.x;
    if (i >= n) return;
    float px = __ldg(x + 3 * i);
    float py = __ldg(x + 3 * i + 1);
    float pz = __ldg(x + 3 * i + 2);
    int pos = atomicAdd(&g_off[bucket_key(px, py, pz)], 1);
    g_xs[pos] = make_float4(px, py, pz, __int_as_float(i));
}

// ---------------------------------------------------------------------------
// bucket-tiled noise kernel: one CTA per bucket, V tiles staged in smem
// ---------------------------------------------------------------------------
// smem layout (float4): V128 [0,125) 5x5x5 | V64 [125,152) 3x3x3
//                       V32 [152,160) 2x2x2 | V16 [160,168) 2x2x2
#define SM_V128 0
#define SM_V64  125
#define SM_V32  152
#define SM_V16  160
#define SM_TOT  168

__global__ void __launch_bounds__(BUCKET_THREADS)
noise_bucket_kernel(const float4* __restrict__ V16,
                    const float4* __restrict__ V32,
                    const float4* __restrict__ V64,
                    const float4* __restrict__ V128,
                    float4* __restrict__ out) {
    int b = blockIdx.x;
    int start = (b == 0) ? 0 : g_off[b - 1];  // g_off holds inclusive ends post-scatter
    int end = g_off[b];
    if (start == end) return;

    int kx = b >> 10, ky = (b >> 5) & 31, kz = b & 31;

    __shared__ float4 sm[SM_TOT];
    int tid = threadIdx.x;

    #pragma unroll
    for (int t0 = 0; t0 < SM_TOT; t0 += BUCKET_THREADS) {
        int t = t0 + tid;
        if (t < SM_TOT) {
            float4 v;
            if (t < SM_V64) {
                int lx = t / 25, ly = (t / 5) % 5, lz = t % 5;
                v = __ldg(V128 + ((4 * kx + lx) * 129 + (4 * ky + ly)) * 129 + (4 * kz + lz));
            } else if (t < SM_V32) {
                int u = t - SM_V64;
                int lx = u / 9, ly = (u / 3) % 3, lz = u % 3;
                v = __ldg(V64 + ((2 * kx + lx) * 65 + (2 * ky + ly)) * 65 + (2 * kz + lz));
            } else if (t < SM_V16) {
                int u = t - SM_V32;
                int lx = (u >> 2) & 1, ly = (u >> 1) & 1, lz = u & 1;
                v = __ldg(V32 + ((kx + lx) * 33 + (ky + ly)) * 33 + (kz + lz));
            } else {
                int u = t - SM_V16;
                int lx = (u >> 2) & 1, ly = (u >> 1) & 1, lz = u & 1;
                v = __ldg(V16 + (((kx >> 1) + lx) * 17 + ((ky >> 1) + ly)) * 17 + ((kz >> 1) + lz));
            }
            sm[t] = v;
        }
    }
    __syncthreads();

    for (int j = start + tid; j < end; j += BUCKET_THREADS) {
        float4 p = g_xs[j];
        float px = p.x, py = p.y, pz = p.z;
        int orig = __float_as_int(p.w);

        float4 acc = noise_smem<16, 2>(sm + SM_V16, kx >> 1, ky >> 1, kz >> 1, px, py, pz);
        float4 t;

        t = noise_smem<32, 2>(sm + SM_V32, kx, ky, kz, px, py, pz);
        acc.x = fmaf(0.5f, t.x, acc.x);
        acc.y = fmaf(0.5f, t.y, acc.y);
        acc.z = fmaf(0.5f, t.z, acc.z);
        acc.w = fmaf(0.5f, t.w, acc.w);

        t = noise_smem<64, 3>(sm + SM_V64, 2 * kx, 2 * ky, 2 * kz, px, py, pz);
        acc.x = fmaf(0.25f, t.x, acc.x);
        acc.y = fmaf(0.25f, t.y, acc.y);
        acc.z = fmaf(0.25f, t.z, acc.z);
        acc.w = fmaf(0.25f, t.w, acc.w);

        t = noise_smem<128, 5>(sm + SM_V128, 4 * kx, 4 * ky, 4 * kz, px, py, pz);
        acc.x = fmaf(0.125f, t.x, acc.x);
        acc.y = fmaf(0.125f, t.y, acc.y);
        acc.z = fmaf(0.125f, t.z, acc.z);
        acc.w = fmaf(0.125f, t.w, acc.w);

        out[orig] = acc;
    }
}

// ---------------------------------------------------------------------------
// fallback (unsorted) if n exceeds static scratch
// ---------------------------------------------------------------------------
__global__ void __launch_bounds__(256)
noise_direct_kernel(const float* __restrict__ x,
                    const float4* __restrict__ V16,
                    const float4* __restrict__ V32,
                    const float4* __restrict__ V64,
                    const float4* __restrict__ V128,
                    float4* __restrict__ out,
                    int n) {
    int i = blockIdx.x * blockDim.x + threadIdx.x;
    if (i >= n) return;
    float px = x[3 * i], py = x[3 * i + 1], pz = x[3 * i + 2];
    float4 acc = noise_level<16>(V16, px, py, pz);
    float4 t;
    t = noise_level<32>(V32, px, py, pz);
    acc.x = fmaf(0.5f, t.x, acc.x); acc.y = fmaf(0.5f, t.y, acc.y);
    acc.z = fmaf(0.5f, t.z, acc.z); acc.w = fmaf(0.5f, t.w, acc.w);
    t = noise_level<64>(V64, px, py, pz);
    acc.x = fmaf(0.25f, t.x, acc.x); acc.y = fmaf(0.25f, t.y, acc.y);
    acc.z = fmaf(0.25f, t.z, acc.z); acc.w = fmaf(0.25f, t.w, acc.w);
    t = noise_level<128>(V128, px, py, pz);
    acc.x = fmaf(0.125f, t.x, acc.x); acc.y = fmaf(0.125f, t.y, acc.y);
    acc.z = fmaf(0.125f, t.z, acc.z); acc.w = fmaf(0.125f, t.w, acc.w);
    out[i] = acc;
}

extern "C" void kernel_launch(void* const* d_in, const int* in_sizes, int n_in,
                              void* d_out, int out_size) {
    const float*  x    = (const float*)d_in[0];
    const float4* V16  = (const float4*)d_in[1];
    const float4* V32  = (const float4*)d_in[2];
    const float4* V64  = (const float4*)d_in[3];
    const float4* V128 = (const float4*)d_in[4];
    float4* out = (float4*)d_out;

    int n = in_sizes[0] / 3;
    int threads = 256;
    int blocks = (n + threads - 1) / threads;

    if (n > MAX_POINTS) {
        noise_direct_kernel<<<blocks, threads>>>(x, V16, V32, V64, V128, out, n);
        return;
    }

    zero_hist_kernel<<<(NB + 255) / 256, 256>>>();
    histo_kernel<<<blocks, threads>>>(x, n);
    scan_kernel<<<1, SCAN_THREADS>>>();
    scatter_kernel<<<blocks, threads>>>(x, n);
    noise_bucket_kernel<<<NB, BUCKET_THREADS>>>(V16, V32, V64, V128, out);
}

// round 5
// speedup vs baseline: 1.2890x; 1.1854x over previous
#include <cuda_runtime.h>

// CompositeValueNoise, bucket-tiled v2:
//   key = coarse 16^3 cell * 8 + fine octant  (== V32 cell, locality-grouped)
//   histo computes per-point rank (atomic) ; scan is warp-shuffle based ;
//   scatter is atomic-free ; noise kernel: 1 CTA per coarse cell (8 V32 cells),
//   stages 14.2KB of V-tiles into smem, evaluates ~488 points from smem.

#define MAX_POINTS 2000000
#define NB 32768
#define NG 4096              // 16^3 coarse groups
#define SCAN_THREADS 1024
#define SCAN_PER 32          // counters per scan thread

__device__ int    g_hist[NB];
__device__ int    g_base[NB + 1];
__device__ int    g_rank[MAX_POINTS];
__device__ float4 g_xs[MAX_POINTS];

// ---------------------------------------------------------------------------
// math helpers
// ---------------------------------------------------------------------------
__device__ __forceinline__ float4 lerp4(const float4 a, const float4 b, const float t) {
    return make_float4(fmaf(t, b.x - a.x, a.x),
                       fmaf(t, b.y - a.y, a.y),
                       fmaf(t, b.z - a.z, a.z),
                       fmaf(t, b.w - a.w, a.w));
}

// Trilerp from smem tile of dim T^3; tile origin = grid point (bx,by,bz) at RES.
template <int RES, int T>
__device__ __forceinline__ float4 noise_smem(const float4* __restrict__ sm,
                                             int bx, int by, int bz,
                                             float px, float py, float pz) {
    const float r = (float)RES;
    float sx = px * r, sy = py * r, sz = pz * r;
    float fx = floorf(sx), fy = floorf(sy), fz = floorf(sz);
    float tx = sx - fx, ty = sy - fy, tz = sz - fz;
    int lx = (int)fx - bx;
    int ly = (int)fy - by;
    int lz = (int)fz - bz;

    float wx = (3.0f - 2.0f * tx) * tx * tx;
    float wy = (3.0f - 2.0f * ty) * ty * ty;
    float wz = (3.0f - 2.0f * tz) * tz * tz;

    int idx = (lx * T + ly) * T + lz;
    float4 c000 = sm[idx];
    float4 c001 = sm[idx + 1];
    float4 c010 = sm[idx + T];
    float4 c011 = sm[idx + T + 1];
    float4 c100 = sm[idx + T * T];
    float4 c101 = sm[idx + T * T + 1];
    float4 c110 = sm[idx + T * T + T];
    float4 c111 = sm[idx + T * T + T + 1];

    float4 az  = lerp4(c000, c001, wz);
    float4 bz4 = lerp4(c010, c011, wz);
    float4 cz  = lerp4(c100, c101, wz);
    float4 dz  = lerp4(c110, c111, wz);
    float4 ay  = lerp4(az, bz4, wy);
    float4 by4 = lerp4(cz, dz, wy);
    return lerp4(ay, by4, wx);
}

// global-gather version (fallback)
template <int RES>
__device__ __forceinline__ float4 noise_level(const float4* __restrict__ V,
                                              float px, float py, float pz) {
    const float r = (float)RES;
    float sx = px * r, sy = py * r, sz = pz * r;
    float fx = floorf(sx), fy = floorf(sy), fz = floorf(sz);
    float tx = sx - fx, ty = sy - fy, tz = sz - fz;
    int ix = min((int)fx, RES - 1);
    int iy = min((int)fy, RES - 1);
    int iz = min((int)fz, RES - 1);
    float wx = (3.0f - 2.0f * tx) * tx * tx;
    float wy = (3.0f - 2.0f * ty) * ty * ty;
    float wz = (3.0f - 2.0f * tz) * tz * tz;
    const int S = RES + 1, SY = S, SX = S * S;
    int base = (ix * S + iy) * S + iz;
    float4 c000 = __ldg(V + base);
    float4 c001 = __ldg(V + base + 1);
    float4 c010 = __ldg(V + base + SY);
    float4 c011 = __ldg(V + base + SY + 1);
    float4 c100 = __ldg(V + base + SX);
    float4 c101 = __ldg(V + base + SX + 1);
    float4 c110 = __ldg(V + base + SX + SY);
    float4 c111 = __ldg(V + base + SX + SY + 1);
    float4 az = lerp4(c000, c001, wz);
    float4 bz = lerp4(c010, c011, wz);
    float4 cz = lerp4(c100, c101, wz);
    float4 dz = lerp4(c110, c111, wz);
    float4 ay = lerp4(az, bz, wy);
    float4 by = lerp4(cz, dz, wy);
    return lerp4(ay, by, wx);
}

// key: coarse 16^3 cell major, fine octant minor -> V32 cell, locality-grouped
__device__ __forceinline__ int bucket_key(float px, float py, float pz) {
    int kx = min((int)(px * 32.0f), 31);
    int ky = min((int)(py * 32.0f), 31);
    int kz = min((int)(pz * 32.0f), 31);
    int coarse = (((kx >> 1) * 16 + (ky >> 1)) * 16) + (kz >> 1);
    int fine = ((kx & 1) << 2) | ((ky & 1) << 1) | (kz & 1);
    return coarse * 8 + fine;
}

// ---------------------------------------------------------------------------
// sort pipeline
// ---------------------------------------------------------------------------
__global__ void zero_hist_kernel() {
    int i = blockIdx.x * blockDim.x + threadIdx.x;
    if (i < NB) g_hist[i] = 0;
}

__global__ void histo_kernel(const float* __restrict__ x, int n) {
    int i = blockIdx.x * blockDim.x + threadIdx.x;
    if (i >= n) return;
    float px = __ldg(x + 3 * i);
    float py = __ldg(x + 3 * i + 1);
    float pz = __ldg(x + 3 * i + 2);
    int key = bucket_key(px, py, pz);
    g_rank[i] = atomicAdd(&g_hist[key], 1);
}

__global__ void __launch_bounds__(SCAN_THREADS)
scan_kernel() {
    __shared__ int wsum[32];
    int tid = threadIdx.x;
    int lane = tid & 31, warp = tid >> 5;
    int base = tid * SCAN_PER;

    int local[SCAN_PER];
    int s = 0;
    #pragma unroll
    for (int j = 0; j < SCAN_PER; j++) { local[j] = g_hist[base + j]; s += local[j]; }

    // warp inclusive scan of per-thread sums
    int v = s;
    #pragma unroll
    for (int off = 1; off < 32; off <<= 1) {
        int t = __shfl_up_sync(0xffffffffu, v, off);
        if (lane >= off) v += t;
    }
    if (lane == 31) wsum[warp] = v;
    __syncthreads();
    if (warp == 0) {
        int w = wsum[lane];
        #pragma unroll
        for (int off = 1; off < 32; off <<= 1) {
            int t = __shfl_up_sync(0xffffffffu, w, off);
            if (lane >= off) w += t;
        }
        wsum[lane] = w;
    }
    __syncthreads();

    int run = v - s + (warp ? wsum[warp - 1] : 0);   // exclusive prefix
    #pragma unroll
    for (int j = 0; j < SCAN_PER; j++) {
        g_base[base + j] = run;
        run += local[j];
    }
    if (tid == SCAN_THREADS - 1) g_base[NB] = run;   // = n
}

__global__ void scatter_kernel(const float* __restrict__ x, int n) {
    int i = blockIdx.x * blockDim.x + threadIdx.x;
    if (i >= n) return;
    float px = __ldg(x + 3 * i);
    float py = __ldg(x + 3 * i + 1);
    float pz = __ldg(x + 3 * i + 2);
    int key = bucket_key(px, py, pz);
    int pos = __ldg(&g_base[key]) + g_rank[i];
    g_xs[pos] = make_float4(px, py, pz, __int_as_float(i));
}

// ---------------------------------------------------------------------------
// grouped noise kernel: one CTA per coarse 16^3 cell (8 V32 cells)
// smem (float4): V128 9^3 @0 (729) | V64 5^3 @729 (125) | V32 3^3 @854 (27)
//                V16 2^3 @881 (8)  -> 889 * 16B = 14224 B
// ---------------------------------------------------------------------------
#define SMG_V128 0
#define SMG_V64  729
#define SMG_V32  854
#define SMG_V16  881
#define SMG_TOT  889
#define GROUP_THREADS 256

__global__ void __launch_bounds__(GROUP_THREADS)
noise_group_kernel(const float4* __restrict__ V16,
                   const float4* __restrict__ V32,
                   const float4* __restrict__ V64,
                   const float4* __restrict__ V128,
                   float4* __restrict__ out) {
    int g = blockIdx.x;
    int start = __ldg(&g_base[g * 8]);
    int end   = __ldg(&g_base[g * 8 + 8]);
    if (start == end) return;

    int cx = g >> 8, cy = (g >> 4) & 15, cz = g & 15;

    __shared__ float4 sm[SMG_TOT];
    int tid = threadIdx.x;

    for (int t = tid; t < SMG_TOT; t += GROUP_THREADS) {
        float4 v;
        if (t < SMG_V64) {
            int lx = t / 81, r = t % 81, ly = r / 9, lz = r % 9;
            v = __ldg(V128 + ((8 * cx + lx) * 129 + (8 * cy + ly)) * 129 + (8 * cz + lz));
        } else if (t < SMG_V32) {
            int u = t - SMG_V64;
            int lx = u / 25, r = u % 25, ly = r / 5, lz = r % 5;
            v = __ldg(V64 + ((4 * cx + lx) * 65 + (4 * cy + ly)) * 65 + (4 * cz + lz));
        } else if (t < SMG_V16) {
            int u = t - SMG_V32;
            int lx = u / 9, ly = (u / 3) % 3, lz = u % 3;
            v = __ldg(V32 + ((2 * cx + lx) * 33 + (2 * cy + ly)) * 33 + (2 * cz + lz));
        } else {
            int u = t - SMG_V16;
            int lx = (u >> 2) & 1, ly = (u >> 1) & 1, lz = u & 1;
            v = __ldg(V16 + ((cx + lx) * 17 + (cy + ly)) * 17 + (cz + lz));
        }
        sm[t] = v;
    }
    __syncthreads();

    for (int j = start + tid; j < end; j += GROUP_THREADS) {
        float4 p = g_xs[j];
        float px = p.x, py = p.y, pz = p.z;
        int orig = __float_as_int(p.w);

        float4 acc = noise_smem<16, 2>(sm + SMG_V16, cx, cy, cz, px, py, pz);
        float4 t;

        t = noise_smem<32, 3>(sm + SMG_V32, 2 * cx, 2 * cy, 2 * cz, px, py, pz);
        acc.x = fmaf(0.5f, t.x, acc.x);
        acc.y = fmaf(0.5f, t.y, acc.y);
        acc.z = fmaf(0.5f, t.z, acc.z);
        acc.w = fmaf(0.5f, t.w, acc.w);

        t = noise_smem<64, 5>(sm + SMG_V64, 4 * cx, 4 * cy, 4 * cz, px, py, pz);
        acc.x = fmaf(0.25f, t.x, acc.x);
        acc.y = fmaf(0.25f, t.y, acc.y);
        acc.z = fmaf(0.25f, t.z, acc.z);
        acc.w = fmaf(0.25f, t.w, acc.w);

        t = noise_smem<128, 9>(sm + SMG_V128, 8 * cx, 8 * cy, 8 * cz, px, py, pz);
        acc.x = fmaf(0.125f, t.x, acc.x);
        acc.y = fmaf(0.125f, t.y, acc.y);
        acc.z = fmaf(0.125f, t.z, acc.z);
        acc.w = fmaf(0.125f, t.w, acc.w);

        out[orig] = acc;
    }
}

// ---------------------------------------------------------------------------
// fallback (unsorted) if n exceeds static scratch
// ---------------------------------------------------------------------------
__global__ void __launch_bounds__(256)
noise_direct_kernel(const float* __restrict__ x,
                    const float4* __restrict__ V16,
                    const float4* __restrict__ V32,
                    const float4* __restrict__ V64,
                    const float4* __restrict__ V128,
                    float4* __restrict__ out,
                    int n) {
    int i = blockIdx.x * blockDim.x + threadIdx.x;
    if (i >= n) return;
    float px = x[3 * i], py = x[3 * i + 1], pz = x[3 * i + 2];
    float4 acc = noise_level<16>(V16, px, py, pz);
    float4 t;
    t = noise_level<32>(V32, px, py, pz);
    acc.x = fmaf(0.5f, t.x, acc.x); acc.y = fmaf(0.5f, t.y, acc.y);
    acc.z = fmaf(0.5f, t.z, acc.z); acc.w = fmaf(0.5f, t.w, acc.w);
    t = noise_level<64>(V64, px, py, pz);
    acc.x = fmaf(0.25f, t.x, acc.x); acc.y = fmaf(0.25f, t.y, acc.y);
    acc.z = fmaf(0.25f, t.z, acc.z); acc.w = fmaf(0.25f, t.w, acc.w);
    t = noise_level<128>(V128, px, py, pz);
    acc.x = fmaf(0.125f, t.x, acc.x); acc.y = fmaf(0.125f, t.y, acc.y);
    acc.z = fmaf(0.125f, t.z, acc.z); acc.w = fmaf(0.125f, t.w, acc.w);
    out[i] = acc;
}

extern "C" void kernel_launch(void* const* d_in, const int* in_sizes, int n_in,
                              void* d_out, int out_size) {
    const float*  x    = (const float*)d_in[0];
    const float4* V16  = (const float4*)d_in[1];
    const float4* V32  = (const float4*)d_in[2];
    const float4* V64  = (const float4*)d_in[3];
    const float4* V128 = (const float4*)d_in[4];
    float4* out = (float4*)d_out;

    int n = in_sizes[0] / 3;
    int threads = 256;
    int blocks = (n + threads - 1) / threads;

    if (n > MAX_POINTS) {
        noise_direct_kernel<<<blocks, threads>>>(x, V16, V32, V64, V128, out, n);
        return;
    }

    zero_hist_kernel<<<(NB + 255) / 256, 256>>>();
    histo_kernel<<<blocks, threads>>>(x, n);
    scan_kernel<<<1, SCAN_THREADS>>>();
    scatter_kernel<<<blocks, threads>>>(x, n);
    noise_group_kernel<<<NG, GROUP_THREADS>>>(V16, V32, V64, V128, out);
}